// round 13
// baseline (speedup 1.0000x reference)
#include <cuda_runtime.h>
#include <math.h>
#include <stdint.h>

#define MM    4095
#define T     9
#define NT    455            // 9 * 455 = 4095
#define NTILE 227            // off-diag tiles per sigma
#define FPAD  228            // padded cell-row length (float2), 228*8 = 1824 (16B mult)
#define INV2  228            // 2*228 == 1 (mod 455)
#define CELLS 81             // T*T
#define HCELL 45             // T*(T+1)/2 : first late-half cell index
#define CPT   8              // columns per CTA (4 threads/slot, 2 cols each, f32x2)
#define THREADS 908          // 227 slots * 4 threads
#define DPAD  82             // padded diag-tile length (float2), 82*8 = 656 (16B mult)
#define SLABP 8194           // floats per cc sub-slab (4096 rows * 2 + 2 pad)
#define NPAIRS (4095LL*2048LL)

typedef unsigned long long u64_t;

// Off-diag rotations: [sigma][cell][m-1] (rows padded to FPAD float2)
__device__ __align__(16) float2 g_csF[(size_t)NT * CELLS * FPAD];   // ~67 MB
// Diagonal-tile rotations: [A][ia*T+ib] (specials at ia==ib), padded rows
__device__ __align__(16) float2 g_csD[NT * DPAD];

__host__ __device__ __forceinline__ constexpr int cell_of(int d, int p) {
    return (d < T) ? d * (d + 1) / 2 + p
                   : HCELL + (d - T) * (3 * T - 1 - d) / 2 + (p - (d - (T - 1)));
}

__global__ void precompute(const float* __restrict__ thetas,
                           const int*   __restrict__ round_theta) {
    long long idx = blockIdx.x * (long long)blockDim.x + threadIdx.x;
    if (idx >= NPAIRS) return;
    int r = (int)(idx >> 11), k = (int)(idx & 2047);
    float th = thetas[round_theta[idx]];
    float s, c; sincosf(th, &s, &c);
    if (k == 0) {                         // special: rows (r, 4095), i = r
        int u = (int)((2048LL * r) % MM);
        int A = u / T, ia = u % T;
        g_csD[A * DPAD + ia * T + ia] = make_float2(c, s);
    } else {
        int a0 = r + k; if (a0 >= MM) a0 -= MM;
        int b0 = r - k; if (b0 < 0)   b0 += MM;
        int i = min(a0, b0), j = max(a0, b0);
        int ui = (int)((2048LL * i) % MM);
        int uj = (int)((2048LL * j) % MM);
        int ua = min(ui, uj), ub = max(ui, uj);
        float sg = (ua == ui) ? s : -s;   // orient for (x = ua-row, y = ub-row)
        int A = ua / T, ia = ua % T;
        int B = ub / T, ib = ub % T;
        if (A == B) {
            g_csD[A * DPAD + ia * T + ib] = make_float2(c, sg);
        } else {
            int d   = ia + ib;
            int sig = A + B; if (sig >= NT) sig -= NT;
            int aD  = (sig * INV2) % NT;
            int mm  = A - aD; if (mm < 0) mm += NT;
            int m   = (mm <= NTILE) ? mm : NT - mm;
            g_csF[((size_t)sig * CELLS + cell_of(d, ia)) * FPAD + (m - 1)]
                = make_float2(c, sg);
        }
    }
}

// Packed Givens rotation on 2 columns: per lane, bit-identical to
// x' = fmaf(c, x, -(s*y)); y' = fmaf(s, x, c*y).
__device__ __forceinline__ void rot2(u64_t& x, u64_t& y, float2 cs) {
    unsigned ci = __float_as_uint(cs.x);
    unsigned si = __float_as_uint(cs.y);
    u64_t c2, s2, t, xo = x;
    asm("mov.b64 %0, {%1, %1};" : "=l"(c2) : "r"(ci));
    asm("mov.b64 %0, {%1, %1};" : "=l"(s2) : "r"(si));
    asm("mul.rn.f32x2 %0, %1, %2;" : "=l"(t) : "l"(s2), "l"(y));
    t ^= 0x8000000080000000ULL;                      // exact negation
    asm("fma.rn.f32x2 %0, %1, %2, %3;" : "=l"(x) : "l"(c2), "l"(xo), "l"(t));
    asm("mul.rn.f32x2 %0, %1, %2;" : "=l"(t) : "l"(c2), "l"(y));
    asm("fma.rn.f32x2 %0, %1, %2, %3;" : "=l"(y) : "l"(s2), "l"(xo), "l"(t));
}

__device__ __forceinline__ void tileAB(int sigma, int m, int& A, int& B) {
    int aD = (sigma * INV2) % NT;
    int a = aD + m; if (a >= NT) a -= NT;
    int b = aD - m; if (b < 0)   b += NT;
    A = min(a, b); B = max(a, b);
}

__device__ __forceinline__ void cpasync16(float* sdst, const char* gsrc) {
    uint32_t sa = (uint32_t)__cvta_generic_to_shared(sdst);
    asm volatile("cp.async.cg.shared.global [%0], [%1], 16;\n" :: "r"(sa), "l"(gsrc));
}
__device__ __forceinline__ void cp_commit() { asm volatile("cp.async.commit_group;\n"); }
__device__ __forceinline__ void cp_wait0()  { asm volatile("cp.async.wait_group 0;\n" ::: "memory"); }

// Stage cells [C0,C1) of sigma into smem buffer. 114 16B-units per cell.
__device__ __forceinline__ void stage(int sig, int C0, int C1, float* buf, int tid) {
    const char* g = (const char*)(g_csF + ((size_t)sig * CELLS + C0) * FPAD);
    const int n16 = (C1 - C0) * (FPAD * 8 / 16);
    for (int u = tid; u < n16; u += THREADS)
        cpasync16(buf + u * 4, g + (size_t)u * 16);
}
// Stage the two diag tiles (aE: 2aE==s, aL: 2aL==s-1) for step s into bufDp.
__device__ __forceinline__ void stage_diag(int s, float* bufDp, int tid) {
    int aE = (s * INV2) % NT;
    int aL = aE - INV2; if (aL < 0) aL += NT;
    const char* gE = (const char*)(g_csD + aE * DPAD);
    const char* gL = (const char*)(g_csD + aL * DPAD);
    if (tid < 41) {                     // 41*16 = 656 = DPAD*8
        cpasync16(bufDp + tid * 4, gE + tid * 16);
        cpasync16(bufDp + DPAD * 2 + tid * 4, gL + tid * 16);
    }
}

// Apply cells [C0,C1) from a buffer whose first cell is C0. bufm = buf + (m-1).
template<int C0, int C1>
__device__ __forceinline__ void chunk_visit(const float2* __restrict__ bufm,
                                            u64_t (&ra)[T], u64_t (&rb)[T]) {
    #pragma unroll
    for (int d = 0; d < 2 * T - 1; ++d) {
        const int plo = (d < T) ? 0 : d - (T - 1);
        const int phi = (d < T) ? d : (T - 1);
        #pragma unroll
        for (int p = plo; p <= phi; ++p) {
            const int cell = cell_of(d, p);
            if (cell >= C0 && cell < C1)
                rot2(ra[p], rb[d - p], bufm[(cell - C0) * FPAD]);
        }
    }
}

// Diagonal phase for step s (4 threads, one column-pair each): early half of
// tile aE (2aE==s), late half of tile aL (2aL==s-1), specials chained through
// row 4095 in exact round order. Runs concurrently with off-diag slots
// (disjoint rows: aE is in no off-diag tile; aL only in tile m=227, whose
// owner executes this first).
__device__ __forceinline__ void visit_diag(float* __restrict__ sm_,
                                           const float2* __restrict__ dbuf,
                                           int s, int cc) {
    int aE = (s * INV2) % NT;
    int aL = aE - INV2; if (aL < 0) aL += NT;
    const float2* csE = dbuf;
    const float2* csL = dbuf + DPAD;
    u64_t re[T], rl[T];
    float* pe = sm_ + cc * SLABP + aE * (T * 2);
    float* pl = sm_ + cc * SLABP + aL * (T * 2);
    u64_t sp = *(u64_t*)(sm_ + cc * SLABP + MM * 2);
    #pragma unroll
    for (int q = 0; q < T; ++q) { re[q] = *(u64_t*)(pe + q * 2);
                                  rl[q] = *(u64_t*)(pl + q * 2); }
    #pragma unroll
    for (int dp = 0; dp < T; ++dp) {                 // round T*s + dp
        #pragma unroll
        for (int p = 0; 2 * p < dp; ++p) rot2(re[p], re[dp - p], csE[p * T + (dp - p)]);
        if ((dp & 1) == 0) rot2(re[dp >> 1], sp, csE[(dp >> 1) * (T + 1)]);
        if (dp <= T - 2) {
            const int dd = dp + T;
            #pragma unroll
            for (int p = dp + 1; 2 * p < dd; ++p) rot2(rl[p], rl[dd - p], csL[p * T + (dd - p)]);
            if ((dd & 1) == 0) rot2(rl[dd >> 1], sp, csL[(dd >> 1) * (T + 1)]);
        }
    }
    #pragma unroll
    for (int q = 0; q < T; ++q) { *(u64_t*)(pe + q * 2) = re[q];
                                  *(u64_t*)(pl + q * 2) = rl[q]; }
    *(u64_t*)(sm_ + cc * SLABP + MM * 2) = sp;
}

__device__ __forceinline__ void loadT(u64_t (&r)[T], const float* p) {
    #pragma unroll
    for (int q = 0; q < T; ++q) r[q] = *(const u64_t*)(p + q * 2);
}
__device__ __forceinline__ void storeT(const u64_t (&r)[T], float* p) {
    #pragma unroll
    for (int q = 0; q < T; ++q) *(u64_t*)(p + q * 2) = r[q];
}

#define SLAB_F (4 * SLABP)                 // 32776 floats = 131104 B
#define DHALF  (2 * DPAD * 2)              // floats per diag parity buffer (328)
#define DBUF_F (2 * DHALF)                 // 656 floats (double-buffered)
#define CBUF_F (14 * FPAD * 2)             // 6384 floats per chunk buffer
#define SMEM_F (SLAB_F + DBUF_F + 2 * CBUF_F)   // 46200 floats = 184800 B

// Pipeline: wait current chunk, barrier, issue next stage, compute from BUF.
#define PIPES(C0, C1, BUF, STG) do {                                           \
    cp_wait0(); __syncthreads();                                               \
    { STG; } cp_commit();                                                      \
    chunk_visit<C0, C1>((const float2*)(BUF) + (m - 1), ra, rb);               \
} while (0)

__global__ void __launch_bounds__(THREADS, 1)
rotmat_kernel(float* __restrict__ out) {
    extern __shared__ float sm[];          // 4 cc-sub-slabs | bufD(x2) | buf0 | buf1
    float* bufD = sm + SLAB_F;
    float* buf0 = bufD + DBUF_F;
    float* buf1 = buf0 + CBUF_F;
    const int c0  = blockIdx.x * CPT;
    const int tid = threadIdx.x;
    const int slot = tid >> 2;             // 0..226
    const int cc   = tid & 3;              // column-pair within slot
    const int m    = slot + 1;             // tile index 1..227

    for (int i = tid; i < SLAB_F; i += THREADS) sm[i] = 0.0f;
    __syncthreads();
    if (tid < CPT) {                       // identity in u-coordinates
        int c = c0 + tid;
        int u = (c == MM) ? MM : (int)((2048LL * c) % MM);
        sm[(tid >> 1) * SLABP + u * 2 + (tid & 1)] = 1.0f;
    }
    __syncthreads();

    u64_t ra[T], rb[T];
    int A, B;

    // ---- Prologue: late half (cells 45..80) of sigma = 454 ----
    stage(NT - 1, 45, 54, buf0, tid); stage_diag(0, bufD, tid); cp_commit();
    tileAB(NT - 1, m, A, B);
    float* pa = sm + cc * SLABP + A * (T * 2);
    float* pb = sm + cc * SLABP + B * (T * 2);
    cp_wait0(); __syncthreads();
    stage(NT - 1, 54, 63, buf1, tid); cp_commit();
    loadT(ra, pa); loadT(rb, pb);
    chunk_visit<45, 54>((const float2*)buf0 + (m - 1), ra, rb);
    PIPES(54, 63, buf1, stage(NT - 1, 63, 72, buf0, tid));
    PIPES(63, 72, buf0, stage(NT - 1, 72, 81, buf1, tid));
    PIPES(72, 81, buf1, stage(0, 0, 14, buf0, tid));
    storeT(ra, pa); storeT(rb, pb);
    __syncthreads();
    // invariant at loop top: chunk (s,[0,14)) in flight -> buf0; diag(s) in bufD[s&1]

    for (int s = 0; s < NT - 1; ++s) {
        tileAB(s, m, A, B);
        pa = sm + cc * SLABP + A * (T * 2);
        pb = sm + cc * SLABP + B * (T * 2);
        cp_wait0(); __syncthreads();
        stage(s, 14, 28, buf1, tid);
        stage_diag(s + 1, bufD + ((s + 1) & 1) * DHALF, tid);
        cp_commit();
        if (slot == NTILE - 1)
            visit_diag(sm, (const float2*)(bufD + (s & 1) * DHALF), s, cc);
        loadT(ra, pa); loadT(rb, pb);
        chunk_visit<0, 14>((const float2*)buf0 + (m - 1), ra, rb);
        PIPES(14, 28, buf1, stage(s, 28, 42, buf0, tid));
        PIPES(28, 42, buf0, stage(s, 42, 56, buf1, tid));
        PIPES(42, 56, buf1, stage(s, 56, 70, buf0, tid));
        PIPES(56, 70, buf0, stage(s, 70, 81, buf1, tid));
        PIPES(70, 81, buf1, stage(s + 1, 0, 14, buf0, tid));
        storeT(ra, pa); storeT(rb, pb);
        __syncthreads();
    }

    // ---- Epilogue: s = 454, early half (cells 0..44) ----
    {
        const int s = NT - 1;
        tileAB(s, m, A, B);
        pa = sm + cc * SLABP + A * (T * 2);
        pb = sm + cc * SLABP + B * (T * 2);
        cp_wait0(); __syncthreads();
        stage(s, 14, 28, buf1, tid); cp_commit();
        if (slot == NTILE - 1)
            visit_diag(sm, (const float2*)(bufD + (s & 1) * DHALF), s, cc);
        loadT(ra, pa); loadT(rb, pb);
        chunk_visit<0, 14>((const float2*)buf0 + (m - 1), ra, rb);
        PIPES(14, 28, buf1, stage(s, 28, 42, buf0, tid));
        PIPES(28, 42, buf0, stage(s, 42, 45, buf1, tid));
        PIPES(42, 45, buf1, { });
        storeT(ra, pa); storeT(rb, pb);
        __syncthreads();
    }

    // Writeback: slab u-row v -> absolute row x = 2v mod 4095 (4095 -> 4095)
    for (int v = tid; v < 4096; v += THREADS) {
        int x = (v == MM) ? MM : ((2 * v) % MM);
        u64_t* dst = (u64_t*)(out + (size_t)x * 4096 + c0);
        #pragma unroll
        for (int k = 0; k < 4; ++k)
            dst[k] = *(const u64_t*)(sm + k * SLABP + v * 2);
    }
}

extern "C" void kernel_launch(void* const* d_in, const int* in_sizes, int n_in,
                              void* d_out, int out_size) {
    const float* thetas      = (const float*)d_in[0];
    const int*   round_theta = (const int*)d_in[3];
    float*       out         = (float*)d_out;
    (void)in_sizes; (void)n_in; (void)out_size;

    const int smem = SMEM_F * (int)sizeof(float);       // 184,800 B
    cudaFuncSetAttribute(rotmat_kernel,
                         cudaFuncAttributeMaxDynamicSharedMemorySize, smem);

    precompute<<<(int)((NPAIRS + 255) / 256), 256>>>(thetas, round_theta);

    rotmat_kernel<<<4096 / CPT, THREADS, smem>>>(out);
}

// round 14
// speedup vs baseline: 1.0126x; 1.0126x over previous
#include <cuda_runtime.h>
#include <math.h>
#include <stdint.h>

#define MM    4095
#define T     9
#define NT    455            // 9 * 455 = 4095
#define NTILE 227            // off-diag tiles per sigma
#define FPAD  228            // padded cell-row length (float2): 228*8 = 1824 B (16-mult)
#define INV2  228            // 2*228 == 1 (mod 455)
#define CELLS 81             // T*T
#define HCELL 45             // T*(T+1)/2 : first late-half cell index
#define CPT   8              // columns per CTA (4 threads/slot, 2 cols each, f32x2)
#define THREADS 908          // 227 slots * 4 threads
#define DPAD  82             // padded diag-tile length (float2): 656 B (16-mult)
#define SLABP 8194           // floats per cc sub-slab (4096 rows * 2 + 2 pad)
#define NPAIRS (4095LL*2048LL)

typedef unsigned long long u64_t;

// Off-diag rotations: [sigma][cell][m-1] (rows padded to FPAD float2)
__device__ __align__(16) float2 g_csF[(size_t)NT * CELLS * FPAD];   // ~67 MB
// Diagonal-tile rotations: [A][ia*T+ib] (specials at ia==ib), padded rows
__device__ __align__(16) float2 g_csD[NT * DPAD];

__host__ __device__ __forceinline__ constexpr int cell_of(int d, int p) {
    return (d < T) ? d * (d + 1) / 2 + p
                   : HCELL + (d - T) * (3 * T - 1 - d) / 2 + (p - (d - (T - 1)));
}

__global__ void precompute(const float* __restrict__ thetas,
                           const int*   __restrict__ round_theta) {
    long long idx = blockIdx.x * (long long)blockDim.x + threadIdx.x;
    if (idx >= NPAIRS) return;
    int r = (int)(idx >> 11), k = (int)(idx & 2047);
    float th = thetas[round_theta[idx]];
    float s, c; sincosf(th, &s, &c);
    if (k == 0) {                         // special: rows (r, 4095), i = r
        int u = (int)((2048LL * r) % MM);
        int A = u / T, ia = u % T;
        g_csD[A * DPAD + ia * T + ia] = make_float2(c, s);
    } else {
        int a0 = r + k; if (a0 >= MM) a0 -= MM;
        int b0 = r - k; if (b0 < 0)   b0 += MM;
        int i = min(a0, b0), j = max(a0, b0);
        int ui = (int)((2048LL * i) % MM);
        int uj = (int)((2048LL * j) % MM);
        int ua = min(ui, uj), ub = max(ui, uj);
        float sg = (ua == ui) ? s : -s;   // orient for (x = ua-row, y = ub-row)
        int A = ua / T, ia = ua % T;
        int B = ub / T, ib = ub % T;
        if (A == B) {
            g_csD[A * DPAD + ia * T + ib] = make_float2(c, sg);
        } else {
            int d   = ia + ib;
            int sig = A + B; if (sig >= NT) sig -= NT;
            int aD  = (sig * INV2) % NT;
            int mm  = A - aD; if (mm < 0) mm += NT;
            int m   = (mm <= NTILE) ? mm : NT - mm;
            g_csF[((size_t)sig * CELLS + cell_of(d, ia)) * FPAD + (m - 1)]
                = make_float2(c, sg);
        }
    }
}

// Packed Givens rotation on 2 columns: per lane, bit-identical to
// x' = fmaf(c, x, -(s*y)); y' = fmaf(s, x, c*y).
__device__ __forceinline__ void rot2(u64_t& x, u64_t& y, float2 cs) {
    unsigned ci = __float_as_uint(cs.x);
    unsigned si = __float_as_uint(cs.y);
    u64_t c2, s2, t, xo = x;
    asm("mov.b64 %0, {%1, %1};" : "=l"(c2) : "r"(ci));
    asm("mov.b64 %0, {%1, %1};" : "=l"(s2) : "r"(si));
    asm("mul.rn.f32x2 %0, %1, %2;" : "=l"(t) : "l"(s2), "l"(y));
    t ^= 0x8000000080000000ULL;                      // exact negation
    asm("fma.rn.f32x2 %0, %1, %2, %3;" : "=l"(x) : "l"(c2), "l"(xo), "l"(t));
    asm("mul.rn.f32x2 %0, %1, %2;" : "=l"(t) : "l"(c2), "l"(y));
    asm("fma.rn.f32x2 %0, %1, %2, %3;" : "=l"(y) : "l"(s2), "l"(xo), "l"(t));
}

__device__ __forceinline__ void tileAB(int sigma, int m, int& A, int& B) {
    int aD = (sigma * INV2) % NT;
    int a = aD + m; if (a >= NT) a -= NT;
    int b = aD - m; if (b < 0)   b += NT;
    A = min(a, b); B = max(a, b);
}

// ---- 1D bulk-async (TMA) staging ----
__device__ __forceinline__ void bulk_cp(uint32_t sdst, const void* gsrc,
                                        unsigned bytes, uint32_t mbar) {
    asm volatile(
        "cp.async.bulk.shared::cta.global.mbarrier::complete_tx::bytes "
        "[%0], [%1], %2, [%3];"
        :: "r"(sdst), "l"(gsrc), "r"(bytes), "r"(mbar) : "memory");
}
__device__ __forceinline__ void expect_tx(uint32_t mbar, unsigned bytes) {
    asm volatile("mbarrier.arrive.expect_tx.shared.b64 _, [%0], %1;"
                 :: "r"(mbar), "r"(bytes) : "memory");
}
__device__ __forceinline__ void mbar_init(uint32_t mbar) {
    asm volatile("mbarrier.init.shared.b64 [%0], %1;" :: "r"(mbar), "r"(1u) : "memory");
}
#define MBWAIT(mbar, ph) do {                                                  \
    unsigned _done = 0;                                                        \
    while (!_done) {                                                           \
        asm volatile("{\n\t.reg .pred p;\n\t"                                  \
            "mbarrier.try_wait.parity.acquire.cta.shared::cta.b64 p, [%1], %2, 0x989680;\n\t" \
            "selp.b32 %0, 1, 0, p;\n\t}"                                       \
            : "=r"(_done) : "r"(mbar), "r"(ph) : "memory");                    \
    }                                                                          \
    (ph) ^= 1u;                                                                \
} while (0)

// Issue a cell-chunk stage (one thread): cells [C0,C1) of sigma -> sbuf.
__device__ __forceinline__ void issue(int sig, int C0, int C1,
                                      uint32_t sbuf, uint32_t mbar) {
    unsigned bytes = (unsigned)(C1 - C0) * 1824u;
    expect_tx(mbar, bytes);
    bulk_cp(sbuf, (const void*)(g_csF + ((size_t)sig * CELLS + C0) * FPAD),
            bytes, mbar);
}
// Same, plus the two diag tiles for step sd bundled into the transaction.
__device__ __forceinline__ void issue_diag(int sig, int C0, int C1,
                                           uint32_t sbuf, uint32_t mbar,
                                           int sd, uint32_t sbufD) {
    unsigned bytes = (unsigned)(C1 - C0) * 1824u;
    expect_tx(mbar, bytes + 1312u);
    bulk_cp(sbuf, (const void*)(g_csF + ((size_t)sig * CELLS + C0) * FPAD),
            bytes, mbar);
    int aE = (sd * INV2) % NT;
    int aL = aE - INV2; if (aL < 0) aL += NT;
    bulk_cp(sbufD,        (const void*)(g_csD + aE * DPAD), 656u, mbar);
    bulk_cp(sbufD + 656u, (const void*)(g_csD + aL * DPAD), 656u, mbar);
}

// Apply cells [C0,C1) from a buffer whose first cell is C0. bufm = buf + (m-1).
template<int C0, int C1>
__device__ __forceinline__ void chunk_visit(const float2* __restrict__ bufm,
                                            u64_t (&ra)[T], u64_t (&rb)[T]) {
    #pragma unroll
    for (int d = 0; d < 2 * T - 1; ++d) {
        const int plo = (d < T) ? 0 : d - (T - 1);
        const int phi = (d < T) ? d : (T - 1);
        #pragma unroll
        for (int p = plo; p <= phi; ++p) {
            const int cell = cell_of(d, p);
            if (cell >= C0 && cell < C1)
                rot2(ra[p], rb[d - p], bufm[(cell - C0) * FPAD]);
        }
    }
}

// Diagonal phase for step s (4 threads = slot 226, one column-pair each):
// early half of tile aE (2aE==s), late half of tile aL (2aL==s-1), specials
// chained through row 4095 in exact round order. Runs concurrently with the
// off-diag slots (aE is in no off-diag tile; aL only in tile m=227, whose
// owner executes this first in program order).
__device__ __forceinline__ void visit_diag(float* __restrict__ sm_,
                                           const float2* __restrict__ dbuf,
                                           int s, int cc) {
    int aE = (s * INV2) % NT;
    int aL = aE - INV2; if (aL < 0) aL += NT;
    const float2* csE = dbuf;
    const float2* csL = dbuf + DPAD;
    u64_t re[T], rl[T];
    float* pe = sm_ + cc * SLABP + aE * (T * 2);
    float* pl = sm_ + cc * SLABP + aL * (T * 2);
    u64_t sp = *(u64_t*)(sm_ + cc * SLABP + MM * 2);
    #pragma unroll
    for (int q = 0; q < T; ++q) { re[q] = *(u64_t*)(pe + q * 2);
                                  rl[q] = *(u64_t*)(pl + q * 2); }
    #pragma unroll
    for (int dp = 0; dp < T; ++dp) {                 // round T*s + dp
        #pragma unroll
        for (int p = 0; 2 * p < dp; ++p) rot2(re[p], re[dp - p], csE[p * T + (dp - p)]);
        if ((dp & 1) == 0) rot2(re[dp >> 1], sp, csE[(dp >> 1) * (T + 1)]);
        if (dp <= T - 2) {
            const int dd = dp + T;
            #pragma unroll
            for (int p = dp + 1; 2 * p < dd; ++p) rot2(rl[p], rl[dd - p], csL[p * T + (dd - p)]);
            if ((dd & 1) == 0) rot2(rl[dd >> 1], sp, csL[(dd >> 1) * (T + 1)]);
        }
    }
    #pragma unroll
    for (int q = 0; q < T; ++q) { *(u64_t*)(pe + q * 2) = re[q];
                                  *(u64_t*)(pl + q * 2) = rl[q]; }
    *(u64_t*)(sm_ + cc * SLABP + MM * 2) = sp;
}

__device__ __forceinline__ void loadT(u64_t (&r)[T], const float* p) {
    #pragma unroll
    for (int q = 0; q < T; ++q) r[q] = *(const u64_t*)(p + q * 2);
}
__device__ __forceinline__ void storeT(const u64_t (&r)[T], float* p) {
    #pragma unroll
    for (int q = 0; q < T; ++q) *(u64_t*)(p + q * 2) = r[q];
}

#define SLAB_F (4 * SLABP)                 // 32776 floats = 131104 B
#define DBUF_F (2 * DPAD * 2)              // 328 floats (aE tile | aL tile)
#define CBUF_F (14 * FPAD * 2)             // 6384 floats = 25536 B per chunk buffer
#define SMEM_F (SLAB_F + DBUF_F + 3 * CBUF_F + 8)   // + mbarrier words
// total bytes = (32776 + 328 + 19152 + 8) * 4 = 209,056

__global__ void __launch_bounds__(THREADS, 1)
rotmat_kernel(float* __restrict__ out) {
    extern __shared__ float sm[];          // 4 cc-sub-slabs | bufD | buf0..2 | mbars
    float* bufD = sm + SLAB_F;
    float* buf0 = bufD + DBUF_F;
    float* buf1 = buf0 + CBUF_F;
    float* buf2 = buf1 + CBUF_F;
    const uint32_t sb    = (uint32_t)__cvta_generic_to_shared(sm);
    const uint32_t sbufD = sb + SLAB_F * 4;
    const uint32_t sbuf0 = sbufD + DBUF_F * 4;
    const uint32_t sbuf1 = sbuf0 + CBUF_F * 4;
    const uint32_t sbuf2 = sbuf1 + CBUF_F * 4;
    const uint32_t mb0   = sbuf2 + CBUF_F * 4;
    const uint32_t mb1   = mb0 + 8;
    const uint32_t mb2   = mb0 + 16;

    const int c0  = blockIdx.x * CPT;
    const int tid = threadIdx.x;
    const int slot = tid >> 2;             // 0..226
    const int cc   = tid & 3;              // column-pair within slot
    const int m    = slot + 1;             // tile index 1..227

    for (int i = tid; i < SLAB_F; i += THREADS) sm[i] = 0.0f;
    if (tid == 0) { mbar_init(mb0); mbar_init(mb1); mbar_init(mb2); }
    __syncthreads();
    if (tid < CPT) {                       // identity in u-coordinates
        int c = c0 + tid;
        int u = (c == MM) ? MM : (int)((2048LL * c) % MM);
        sm[(tid >> 1) * SLABP + u * 2 + (tid & 1)] = 1.0f;
    }
    __syncthreads();
    if (tid == 0) {                        // prime the pipeline (lookahead 2)
        issue(NT - 1, 45, 59, sbuf0, mb0);
        issue(NT - 1, 59, 73, sbuf1, mb1);
    }

    unsigned ph0 = 0, ph1 = 0, ph2 = 0;
    u64_t ra[T], rb[T];
    int A, B;

    // ---- Prologue: late half (cells 45..80) of sigma = 454 ----
    tileAB(NT - 1, m, A, B);
    float* pa = sm + cc * SLABP + A * (T * 2);
    float* pb = sm + cc * SLABP + B * (T * 2);
    __syncthreads();
    if (tid == 0) issue(NT - 1, 73, 81, sbuf2, mb2);
    MBWAIT(mb0, ph0);
    loadT(ra, pa); loadT(rb, pb);
    chunk_visit<45, 59>((const float2*)buf0 + (m - 1), ra, rb);
    __syncthreads();
    if (tid == 0) issue_diag(0, 0, 14, sbuf0, mb0, 0, sbufD);
    MBWAIT(mb1, ph1);
    chunk_visit<59, 73>((const float2*)buf1 + (m - 1), ra, rb);
    __syncthreads();
    if (tid == 0) issue(0, 14, 28, sbuf1, mb1);
    MBWAIT(mb2, ph2);
    chunk_visit<73, 81>((const float2*)buf2 + (m - 1), ra, rb);
    storeT(ra, pa); storeT(rb, pb);
    // invariant at loop top: (s,ch0)+diag(s) -> buf0/bufD and (s,ch1) -> buf1 issued

    for (int s = 0; s < NT - 1; ++s) {
        tileAB(s, m, A, B);
        pa = sm + cc * SLABP + A * (T * 2);
        pb = sm + cc * SLABP + B * (T * 2);
        __syncthreads();
        if (tid == 0) issue(s, 28, 42, sbuf2, mb2);
        MBWAIT(mb0, ph0);
        if (slot == NTILE - 1) visit_diag(sm, (const float2*)bufD, s, cc);
        loadT(ra, pa); loadT(rb, pb);
        chunk_visit<0, 14>((const float2*)buf0 + (m - 1), ra, rb);
        __syncthreads();
        if (tid == 0) issue(s, 42, 56, sbuf0, mb0);
        MBWAIT(mb1, ph1);
        chunk_visit<14, 28>((const float2*)buf1 + (m - 1), ra, rb);
        __syncthreads();
        if (tid == 0) issue(s, 56, 70, sbuf1, mb1);
        MBWAIT(mb2, ph2);
        chunk_visit<28, 42>((const float2*)buf2 + (m - 1), ra, rb);
        __syncthreads();
        if (tid == 0) issue(s, 70, 81, sbuf2, mb2);
        MBWAIT(mb0, ph0);
        chunk_visit<42, 56>((const float2*)buf0 + (m - 1), ra, rb);
        __syncthreads();
        if (tid == 0) issue_diag(s + 1, 0, 14, sbuf0, mb0, s + 1, sbufD);
        MBWAIT(mb1, ph1);
        chunk_visit<56, 70>((const float2*)buf1 + (m - 1), ra, rb);
        __syncthreads();
        if (tid == 0) issue(s + 1, 14, 28, sbuf1, mb1);
        MBWAIT(mb2, ph2);
        chunk_visit<70, 81>((const float2*)buf2 + (m - 1), ra, rb);
        storeT(ra, pa); storeT(rb, pb);
    }

    // ---- Epilogue: s = 454, early half (cells 0..44) ----
    {
        const int s = NT - 1;
        tileAB(s, m, A, B);
        pa = sm + cc * SLABP + A * (T * 2);
        pb = sm + cc * SLABP + B * (T * 2);
        __syncthreads();
        if (tid == 0) issue(s, 28, 42, sbuf2, mb2);
        MBWAIT(mb0, ph0);
        if (slot == NTILE - 1) visit_diag(sm, (const float2*)bufD, s, cc);
        loadT(ra, pa); loadT(rb, pb);
        chunk_visit<0, 14>((const float2*)buf0 + (m - 1), ra, rb);
        __syncthreads();
        if (tid == 0) issue(s, 42, 45, sbuf0, mb0);
        MBWAIT(mb1, ph1);
        chunk_visit<14, 28>((const float2*)buf1 + (m - 1), ra, rb);
        MBWAIT(mb2, ph2);
        chunk_visit<28, 42>((const float2*)buf2 + (m - 1), ra, rb);
        MBWAIT(mb0, ph0);
        chunk_visit<42, 45>((const float2*)buf0 + (m - 1), ra, rb);
        storeT(ra, pa); storeT(rb, pb);
        __syncthreads();
    }

    // Writeback: slab u-row v -> absolute row x = 2v mod 4095 (4095 -> 4095)
    for (int v = tid; v < 4096; v += THREADS) {
        int x = (v == MM) ? MM : ((2 * v) % MM);
        u64_t* dst = (u64_t*)(out + (size_t)x * 4096 + c0);
        #pragma unroll
        for (int k = 0; k < 4; ++k)
            dst[k] = *(const u64_t*)(sm + k * SLABP + v * 2);
    }
}

extern "C" void kernel_launch(void* const* d_in, const int* in_sizes, int n_in,
                              void* d_out, int out_size) {
    const float* thetas      = (const float*)d_in[0];
    const int*   round_theta = (const int*)d_in[3];
    float*       out         = (float*)d_out;
    (void)in_sizes; (void)n_in; (void)out_size;

    const int smem = SMEM_F * (int)sizeof(float);       // 209,056 B
    cudaFuncSetAttribute(rotmat_kernel,
                         cudaFuncAttributeMaxDynamicSharedMemorySize, smem);

    precompute<<<(int)((NPAIRS + 255) / 256), 256>>>(thetas, round_theta);

    rotmat_kernel<<<4096 / CPT, THREADS, smem>>>(out);
}